// round 4
// baseline (speedup 1.0000x reference)
#include <cuda_runtime.h>
#include <cuda_fp16.h>
#include <cstdint>

#define DI __device__ __forceinline__

// ---------------- problem constants ----------------
constexpr int T    = 441000;
constexpr int L    = 44100;
constexpr int TILE = 128;
constexpr int NT   = (T + TILE - 1) / TILE;   // 3446 output tiles
constexpr int NC   = 346;                     // K chunks of 128 taps
constexpr int PAD  = 346;                     // zero x-blocks for causal history
constexpr int NXB  = NT + PAD;                // 3792
constexpr int G    = 4;                       // output tiles per CTA
constexpr int NGRP = (NT + G - 1) / G;        // 862 CTAs

constexpr int S    = 136;                     // padded row stride in halves (272B)
constexpr int WIMG = 128 * S;                 // 17408 halves = 34816 B per W chunk image
constexpr int XIMG = 32 * S;                  // 4352 halves  = 8704 B per x block image

// packed global scratch (linear images of the smem tiles)
__device__ __align__(128) __half g_w[(size_t)NC * WIMG];   // 12.0 MB
__device__ __align__(128) __half g_x[(size_t)NXB * XIMG];  // 33.0 MB

// ---------------- smem layout ----------------
constexpr int OFF_W   = 0;                    // 2 x 34816 double buffer
constexpr int OFF_X   = 2 * 34816;            // 69632 : ring of 8 x 8704
constexpr int SMEM_BYTES = OFF_X + 8 * 8704;  // 139264
// epilogue reuses [0, 67584) as float es[4][128][33]

// ---------------- PTX helpers ----------------
DI uint32_t smem_u32(const void* p) {
    uint32_t a;
    asm("{ .reg .u64 t; cvta.to.shared.u64 t, %1; cvt.u32.u64 %0, t; }" : "=r"(a) : "l"(p));
    return a;
}
DI void cp16(uint32_t saddr, const void* gaddr) {
    asm volatile("cp.async.cg.shared.global [%0], [%1], 16;" :: "r"(saddr), "l"(gaddr));
}
DI void cp_commit() { asm volatile("cp.async.commit_group;" ::: "memory"); }
DI void cp_wait1()  { asm volatile("cp.async.wait_group 1;" ::: "memory"); }
DI void cp_wait0()  { asm volatile("cp.async.wait_group 0;" ::: "memory"); }

DI void ldsm4(uint32_t& r0, uint32_t& r1, uint32_t& r2, uint32_t& r3, uint32_t a) {
    asm volatile("ldmatrix.sync.aligned.m8n8.x4.shared.b16 {%0,%1,%2,%3}, [%4];"
                 : "=r"(r0), "=r"(r1), "=r"(r2), "=r"(r3) : "r"(a));
}
DI void mma16816(float* c, uint32_t a0, uint32_t a1, uint32_t a2, uint32_t a3,
                 uint32_t b0, uint32_t b1) {
    asm volatile(
        "mma.sync.aligned.m16n8k16.row.col.f32.f16.f16.f32 "
        "{%0,%1,%2,%3}, {%4,%5,%6,%7}, {%8,%9}, {%0,%1,%2,%3};"
        : "+f"(c[0]), "+f"(c[1]), "+f"(c[2]), "+f"(c[3])
        : "r"(a0), "r"(a1), "r"(a2), "r"(a3), "r"(b0), "r"(b1));
}

// ---------------- pack kernels ----------------
// W chunk c: W[i][m] = ir[128c + i - m], padded rows of S halves
__global__ void __launch_bounds__(256) pack_w_kernel(const float* __restrict__ ir) {
    const int c = blockIdx.x;
    __half* dst = g_w + (size_t)c * WIMG;
    for (int e = threadIdx.x; e < WIMG; e += 256) {
        int i = e / S, m = e % S;
        float v = 0.f;
        if (m < 128) {
            int idx = 128 * c + i - m;
            if (idx >= 0 && idx < L) v = ir[idx];
        }
        dst[e] = __float2half_rn(v);
    }
}
// x block blk (tile tb = blk - PAD): X[b][j] = x[b*T + tb*128 + j]
__global__ void __launch_bounds__(256) pack_x_kernel(const float* __restrict__ x) {
    const int blk = blockIdx.x;
    const int tb  = blk - PAD;
    __half* dst = g_x + (size_t)blk * XIMG;
    for (int e = threadIdx.x; e < XIMG; e += 256) {
        int b = e / S, j = e % S;
        float v = 0.f;
        if (j < 128 && tb >= 0) {
            int n = tb * TILE + j;
            if (n < T) v = x[(size_t)b * T + n];
        }
        dst[e] = __float2half_rn(v);
    }
}

// ---------------- main GEMM-conv kernel ----------------
__global__ void __launch_bounds__(256, 1) conv_main(const float* __restrict__ x,
                                                    const float* __restrict__ wetp,
                                                    float* __restrict__ out) {
    extern __shared__ __align__(128) char smem[];
    const uint32_t sb  = smem_u32(smem);
    const int tid  = threadIdx.x;
    const int wid  = tid >> 5;
    const int lane = tid & 31;

    const int t0 = blockIdx.x * G;
    int gact = NT - t0; if (gact > G) gact = G;
    const int Gact = gact;

    const int mytile = wid >> 1;
    const int mbase  = (wid & 1) * 64;
    const bool active = (mytile < Gact);

    // lane-invariant ldmatrix offsets (in halves)
    const uint32_t aoff = (uint32_t)((lane & 15) * S + (lane >> 4) * 8);
    // B (non-trans): lanes0-7 -> n0-7/k, 8-15 -> n0-7/k+8, 16-23 -> n8-15/k, 24-31 -> n8-15/k+8
    const uint32_t boff = (uint32_t)(((lane & 7) + ((lane >> 4) << 3)) * S + ((lane >> 3) & 1) * 8);

    float acc[4][4][4];
    #pragma unroll
    for (int mi = 0; mi < 4; mi++)
        #pragma unroll
        for (int ni = 0; ni < 4; ni++)
            #pragma unroll
            for (int r = 0; r < 4; r++) acc[mi][ni][r] = 0.f;

    // ---- async loaders (all 256 threads) ----
    auto loadW = [&](int c) {
        const char* src = (const char*)(g_w + (size_t)c * WIMG);
        uint32_t dst = sb + OFF_W + (uint32_t)(c & 1) * 34816u;
        for (int v = tid; v < 2176; v += 256)
            cp16(dst + v * 16u, src + v * 16);
    };
    auto loadX = [&](int blk) {
        const char* src = (const char*)(g_x + (size_t)blk * XIMG);
        uint32_t dst = sb + OFF_X + (uint32_t)(blk & 7) * 8704u;
        for (int v = tid; v < 544; v += 256)
            cp16(dst + v * 16u, src + v * 16);
    };

    // prologue: chunk 0 W + the Gact active x blocks
    loadW(0);
    for (int g = 0; g < Gact; g++) loadX(t0 + PAD + g);
    cp_commit();

    for (int c = 0; c < NC; c++) {
        if (c + 1 < NC) {
            loadW(c + 1);
            loadX(t0 + PAD - (c + 1));
        }
        cp_commit();
        cp_wait1();
        __syncthreads();

        if (active) {
            const uint32_t wbuf = sb + OFF_W + (uint32_t)(c & 1) * 34816u;
            const int blk = t0 + PAD + mytile - c;
            const uint32_t xbuf = sb + OFF_X + (uint32_t)(blk & 7) * 8704u;

            #pragma unroll 2
            for (int ks = 0; ks < 8; ks++) {
                const uint32_t k = (uint32_t)ks * 16u;
                uint32_t a[4][4];
                #pragma unroll
                for (int mi = 0; mi < 4; mi++) {
                    uint32_t ad = wbuf + (((uint32_t)(mbase + mi * 16) * S) + aoff + k) * 2u;
                    ldsm4(a[mi][0], a[mi][1], a[mi][2], a[mi][3], ad);
                }
                uint32_t b[4][2];
                {
                    uint32_t bd0 = xbuf + (boff + k) * 2u;
                    ldsm4(b[0][0], b[0][1], b[1][0], b[1][1], bd0);
                    uint32_t bd1 = bd0 + (uint32_t)(16 * S) * 2u;
                    ldsm4(b[2][0], b[2][1], b[3][0], b[3][1], bd1);
                }
                #pragma unroll
                for (int mi = 0; mi < 4; mi++)
                    #pragma unroll
                    for (int ni = 0; ni < 4; ni++)
                        mma16816(acc[mi][ni], a[mi][0], a[mi][1], a[mi][2], a[mi][3],
                                 b[ni][0], b[ni][1]);
            }
        }
        __syncthreads();
    }

    cp_wait0();
    __syncthreads();

    // ---- epilogue: transpose accums through smem, coalesced fused store ----
    float* es = (float*)smem;   // es[tile][row 128][b 33-padded]
    if (active) {
        const int r0l = lane >> 2;
        const int c0l = (lane & 3) * 2;
        #pragma unroll
        for (int mi = 0; mi < 4; mi++) {
            const int rb = mbase + mi * 16;
            #pragma unroll
            for (int ni = 0; ni < 4; ni++) {
                const int cb = ni * 8 + c0l;
                float* base = es + (size_t)mytile * 4224;
                base[(rb + r0l) * 33 + cb]     = acc[mi][ni][0];
                base[(rb + r0l) * 33 + cb + 1] = acc[mi][ni][1];
                base[(rb + r0l + 8) * 33 + cb]     = acc[mi][ni][2];
                base[(rb + r0l + 8) * 33 + cb + 1] = acc[mi][ni][3];
            }
        }
    }
    __syncthreads();

    const float wv  = wetp[0];
    const float wet = 1.f / (1.f + __expf(-wv));
    const float dry = 1.f - wet;

    const int tot = Gact * 32 * 128;
    for (int e = tid; e < tot; e += 256) {
        const int tile = e >> 12;
        const int rem  = e & 4095;
        const int b    = rem >> 7;
        const int i    = rem & 127;
        const int n    = (t0 + tile) * TILE + i;
        if (n < T) {
            const size_t idx = (size_t)b * T + n;
            out[idx] = dry * x[idx] + wet * es[(size_t)tile * 4224 + i * 33 + b];
        }
    }
}

// ---------------- launch ----------------
extern "C" void kernel_launch(void* const* d_in, const int* in_sizes, int n_in,
                              void* d_out, int out_size) {
    const float* x    = (const float*)d_in[0];
    const float* ir   = (const float*)d_in[1];
    const float* wetp = (const float*)d_in[2];
    float* out        = (float*)d_out;

    cudaFuncSetAttribute(conv_main, cudaFuncAttributeMaxDynamicSharedMemorySize, SMEM_BYTES);

    pack_w_kernel<<<NC, 256>>>(ir);
    pack_x_kernel<<<NXB, 256>>>(x);
    conv_main<<<NGRP, 256, SMEM_BYTES>>>(x, wetp, out);
}

// round 5
// speedup vs baseline: 1.1100x; 1.1100x over previous
#include <cuda_runtime.h>
#include <cuda_fp16.h>
#include <cstdint>

#define DI __device__ __forceinline__

// ---------------- problem constants ----------------
constexpr int T    = 441000;
constexpr int L    = 44100;
constexpr int TILE = 128;
constexpr int NT   = (T + TILE - 1) / TILE;   // 3446 output tiles
constexpr int NC   = 346;                     // K chunks of 128 taps
constexpr int PAD  = 346;                     // zero x-blocks for causal history
constexpr int NXB  = NT + PAD;                // 3792
constexpr int G    = 8;                       // output tiles per CTA
constexpr int NGRP = (NT + G - 1) / G;        // 431 CTAs

constexpr int S    = 136;                     // padded row stride in halves (272B)
constexpr int WIMG = 128 * S;                 // 17408 halves = 34816 B per W chunk image
constexpr int XIMG = 32 * S;                  // 4352 halves  = 8704 B per x block image
constexpr int XRING = 16;

// packed global scratch (linear images of the smem tiles)
__device__ __align__(128) __half g_w[(size_t)NC * WIMG];   // 12.0 MB
__device__ __align__(128) __half g_x[(size_t)NXB * XIMG];  // 33.0 MB

// ---------------- smem layout ----------------
constexpr int OFF_W   = 0;                       // 2 x 34816 double buffer
constexpr int OFF_X   = 2 * 34816;               // 69632 : ring of 16 x 8704
constexpr int SMEM_BYTES = OFF_X + XRING * 8704; // 208896
// epilogue reuses [0, 135168) as float es[8][128][33]

// ---------------- PTX helpers ----------------
DI uint32_t smem_u32(const void* p) {
    uint32_t a;
    asm("{ .reg .u64 t; cvta.to.shared.u64 t, %1; cvt.u32.u64 %0, t; }" : "=r"(a) : "l"(p));
    return a;
}
DI void cp16(uint32_t saddr, const void* gaddr) {
    asm volatile("cp.async.cg.shared.global [%0], [%1], 16;" :: "r"(saddr), "l"(gaddr));
}
DI void cp_commit() { asm volatile("cp.async.commit_group;" ::: "memory"); }
DI void cp_wait1()  { asm volatile("cp.async.wait_group 1;" ::: "memory"); }
DI void cp_wait0()  { asm volatile("cp.async.wait_group 0;" ::: "memory"); }

DI void ldsm4(uint32_t& r0, uint32_t& r1, uint32_t& r2, uint32_t& r3, uint32_t a) {
    asm volatile("ldmatrix.sync.aligned.m8n8.x4.shared.b16 {%0,%1,%2,%3}, [%4];"
                 : "=r"(r0), "=r"(r1), "=r"(r2), "=r"(r3) : "r"(a));
}
DI void mma16816(float* c, uint32_t a0, uint32_t a1, uint32_t a2, uint32_t a3,
                 uint32_t b0, uint32_t b1) {
    asm volatile(
        "mma.sync.aligned.m16n8k16.row.col.f32.f16.f16.f32 "
        "{%0,%1,%2,%3}, {%4,%5,%6,%7}, {%8,%9}, {%0,%1,%2,%3};"
        : "+f"(c[0]), "+f"(c[1]), "+f"(c[2]), "+f"(c[3])
        : "r"(a0), "r"(a1), "r"(a2), "r"(a3), "r"(b0), "r"(b1));
}

// ---------------- pack kernels ----------------
// W chunk c: W[i][m] = ir[128c + i - m], padded rows of S halves
__global__ void __launch_bounds__(256) pack_w_kernel(const float* __restrict__ ir) {
    const int c = blockIdx.x;
    __half* dst = g_w + (size_t)c * WIMG;
    for (int e = threadIdx.x; e < WIMG; e += 256) {
        int i = e / S, m = e % S;
        float v = 0.f;
        if (m < 128) {
            int idx = 128 * c + i - m;
            if (idx >= 0 && idx < L) v = ir[idx];
        }
        dst[e] = __float2half_rn(v);
    }
}
// x block blk (tile tb = blk - PAD): X[b][j] = x[b*T + tb*128 + j]
__global__ void __launch_bounds__(256) pack_x_kernel(const float* __restrict__ x) {
    const int blk = blockIdx.x;
    const int tb  = blk - PAD;
    __half* dst = g_x + (size_t)blk * XIMG;
    for (int e = threadIdx.x; e < XIMG; e += 256) {
        int b = e / S, j = e % S;
        float v = 0.f;
        if (j < 128 && tb >= 0) {
            int n = tb * TILE + j;
            if (n < T) v = x[(size_t)b * T + n];
        }
        dst[e] = __float2half_rn(v);
    }
}

// ---------------- main GEMM-conv kernel ----------------
__global__ void __launch_bounds__(256, 1) conv_main(const float* __restrict__ x,
                                                    const float* __restrict__ wetp,
                                                    float* __restrict__ out) {
    extern __shared__ __align__(128) char smem[];
    const uint32_t sb  = smem_u32(smem);
    const int tid  = threadIdx.x;
    const int wid  = tid >> 5;
    const int lane = tid & 31;

    const int t0 = blockIdx.x * G;
    int gact = NT - t0; if (gact > G) gact = G;
    const int Gact = gact;

    const int mbase  = (wid & 1) * 64;     // M-slice of this warp
    const int tl0    = (wid >> 1) * 2;     // first of 2 tiles for this warp
    const bool act0  = (tl0 < Gact);
    const bool act1  = (tl0 + 1 < Gact);

    // lane-invariant ldmatrix offsets (in halves)
    const uint32_t aoff = (uint32_t)((lane & 15) * S + (lane >> 4) * 8);
    // B (non-trans): lanes0-7 -> n0-7/k, 8-15 -> n0-7/k+8, 16-23 -> n8-15/k, 24-31 -> n8-15/k+8
    const uint32_t boff = (uint32_t)(((lane & 7) + ((lane >> 4) << 3)) * S + ((lane >> 3) & 1) * 8);

    float acc[2][4][4][4];
    #pragma unroll
    for (int j = 0; j < 2; j++)
        #pragma unroll
        for (int mi = 0; mi < 4; mi++)
            #pragma unroll
            for (int ni = 0; ni < 4; ni++)
                #pragma unroll
                for (int r = 0; r < 4; r++) acc[j][mi][ni][r] = 0.f;

    // ---- async loaders (all 256 threads) ----
    auto loadW = [&](int c) {
        const char* src = (const char*)(g_w + (size_t)c * WIMG);
        uint32_t dst = sb + OFF_W + (uint32_t)(c & 1) * 34816u;
        for (int v = tid; v < 2176; v += 256)
            cp16(dst + v * 16u, src + v * 16);
    };
    auto loadX = [&](int blk) {
        const char* src = (const char*)(g_x + (size_t)blk * XIMG);
        uint32_t dst = sb + OFF_X + (uint32_t)(blk & (XRING - 1)) * 8704u;
        for (int v = tid; v < 544; v += 256)
            cp16(dst + v * 16u, src + v * 16);
    };

    // prologue: chunk 0 W + the Gact active x blocks
    loadW(0);
    for (int g = 0; g < Gact; g++) loadX(t0 + PAD + g);
    cp_commit();

    for (int c = 0; c < NC; c++) {
        if (c + 1 < NC) {
            loadW(c + 1);
            loadX(t0 + PAD - (c + 1));
        }
        cp_commit();
        cp_wait1();
        __syncthreads();

        {
            const uint32_t wbuf = sb + OFF_W + (uint32_t)(c & 1) * 34816u;
            const int blk0 = t0 + PAD + tl0 - c;
            const uint32_t xbuf0 = sb + OFF_X + (uint32_t)(blk0 & (XRING - 1)) * 8704u;
            const uint32_t xbuf1 = sb + OFF_X + (uint32_t)((blk0 + 1) & (XRING - 1)) * 8704u;

            #pragma unroll 2
            for (int ks = 0; ks < 8; ks++) {
                const uint32_t k = (uint32_t)ks * 16u;
                uint32_t a[4][4];
                #pragma unroll
                for (int mi = 0; mi < 4; mi++) {
                    uint32_t ad = wbuf + (((uint32_t)(mbase + mi * 16) * S) + aoff + k) * 2u;
                    ldsm4(a[mi][0], a[mi][1], a[mi][2], a[mi][3], ad);
                }
                uint32_t b0[4][2], b1[4][2];
                if (act0) {
                    uint32_t bd = xbuf0 + (boff + k) * 2u;
                    ldsm4(b0[0][0], b0[0][1], b0[1][0], b0[1][1], bd);
                    ldsm4(b0[2][0], b0[2][1], b0[3][0], b0[3][1], bd + (uint32_t)(16 * S) * 2u);
                }
                if (act1) {
                    uint32_t bd = xbuf1 + (boff + k) * 2u;
                    ldsm4(b1[0][0], b1[0][1], b1[1][0], b1[1][1], bd);
                    ldsm4(b1[2][0], b1[2][1], b1[3][0], b1[3][1], bd + (uint32_t)(16 * S) * 2u);
                }
                if (act0) {
                    #pragma unroll
                    for (int mi = 0; mi < 4; mi++)
                        #pragma unroll
                        for (int ni = 0; ni < 4; ni++)
                            mma16816(acc[0][mi][ni], a[mi][0], a[mi][1], a[mi][2], a[mi][3],
                                     b0[ni][0], b0[ni][1]);
                }
                if (act1) {
                    #pragma unroll
                    for (int mi = 0; mi < 4; mi++)
                        #pragma unroll
                        for (int ni = 0; ni < 4; ni++)
                            mma16816(acc[1][mi][ni], a[mi][0], a[mi][1], a[mi][2], a[mi][3],
                                     b1[ni][0], b1[ni][1]);
                }
            }
        }
        __syncthreads();
    }

    cp_wait0();
    __syncthreads();

    // ---- epilogue: transpose accums through smem, coalesced fused store ----
    float* es = (float*)smem;   // es[tile][row 128][b 33-padded]
    {
        const int r0l = lane >> 2;
        const int c0l = (lane & 3) * 2;
        #pragma unroll
        for (int j = 0; j < 2; j++) {
            if (tl0 + j >= Gact) break;
            float* base = es + (size_t)(tl0 + j) * 4224;
            #pragma unroll
            for (int mi = 0; mi < 4; mi++) {
                const int rb = mbase + mi * 16;
                #pragma unroll
                for (int ni = 0; ni < 4; ni++) {
                    const int cb = ni * 8 + c0l;
                    base[(rb + r0l) * 33 + cb]         = acc[j][mi][ni][0];
                    base[(rb + r0l) * 33 + cb + 1]     = acc[j][mi][ni][1];
                    base[(rb + r0l + 8) * 33 + cb]     = acc[j][mi][ni][2];
                    base[(rb + r0l + 8) * 33 + cb + 1] = acc[j][mi][ni][3];
                }
            }
        }
    }
    __syncthreads();

    const float wv  = wetp[0];
    const float wet = 1.f / (1.f + __expf(-wv));
    const float dry = 1.f - wet;

    const int tot = Gact * 32 * 128;
    for (int e = tid; e < tot; e += 256) {
        const int tile = e >> 12;
        const int rem  = e & 4095;
        const int b    = rem >> 7;
        const int i    = rem & 127;
        const int n    = (t0 + tile) * TILE + i;
        if (n < T) {
            const size_t idx = (size_t)b * T + n;
            out[idx] = dry * x[idx] + wet * es[(size_t)tile * 4224 + i * 33 + b];
        }
    }
}

// ---------------- launch ----------------
extern "C" void kernel_launch(void* const* d_in, const int* in_sizes, int n_in,
                              void* d_out, int out_size) {
    const float* x    = (const float*)d_in[0];
    const float* ir   = (const float*)d_in[1];
    const float* wetp = (const float*)d_in[2];
    float* out        = (float*)d_out;

    cudaFuncSetAttribute(conv_main, cudaFuncAttributeMaxDynamicSharedMemorySize, SMEM_BYTES);

    pack_w_kernel<<<NC, 256>>>(ir);
    pack_x_kernel<<<NXB, 256>>>(x);
    conv_main<<<NGRP, 256, SMEM_BYTES>>>(x, wetp, out);
}

// round 6
// speedup vs baseline: 4.7278x; 4.2592x over previous
#include <cuda_runtime.h>
#include <cstdint>
#include <math.h>

#define DI __device__ __forceinline__

// ---------------- problem constants ----------------
constexpr int T     = 441000;
constexpr int L     = 44100;
constexpr int BATCH = 32;
constexpr int NFFT  = 8192;
constexpr int HOP   = 4096;
constexpr int NBLK  = 108;              // ceil(T / HOP)
constexpr int NP    = 11;               // ceil(L / HOP) IR partitions
constexpr int NPAIR = BATCH / 2;        // 16 complex-packed row pairs

constexpr int SMEMB = 4 * NFFT * 4;     // 131072 B: re0,im0,re1,im1

// ---------------- global scratch ----------------
__device__ float2 g_spec[(size_t)NPAIR * NBLK * NFFT];  // 108 MB
__device__ float2 g_H[(size_t)NP * NFFT];               // 704 KB (prescaled by 1/NFFT)
__device__ float2 g_tw[NFFT];                           // e^{-2pi i t / NFFT}

// ---------------- register DFTs (sign sg=+1 fwd e^{-}, sg=-1 inv e^{+}) ----
DI void dft8(float* xr, float* xi, float sg) {
    const float c = 0.70710678118654752f;
    float t0r = xr[0] + xr[4], t0i = xi[0] + xi[4];
    float t1r = xr[0] - xr[4], t1i = xi[0] - xi[4];
    float t2r = xr[2] + xr[6], t2i = xi[2] + xi[6];
    float t3r = xr[2] - xr[6], t3i = xi[2] - xi[6];
    float w3r = sg * t3i, w3i = -sg * t3r;              // W4 * t3
    float E0r = t0r + t2r, E0i = t0i + t2i;
    float E1r = t1r + w3r, E1i = t1i + w3i;
    float E2r = t0r - t2r, E2i = t0i - t2i;
    float E3r = t1r - w3r, E3i = t1i - w3i;
    float u0r = xr[1] + xr[5], u0i = xi[1] + xi[5];
    float u1r = xr[1] - xr[5], u1i = xi[1] - xi[5];
    float u2r = xr[3] + xr[7], u2i = xi[3] + xi[7];
    float u3r = xr[3] - xr[7], u3i = xi[3] - xi[7];
    float v3r = sg * u3i, v3i = -sg * u3r;
    float O0r = u0r + u2r, O0i = u0i + u2i;
    float O1r = u1r + v3r, O1i = u1i + v3i;
    float O2r = u0r - u2r, O2i = u0i - u2i;
    float O3r = u1r - v3r, O3i = u1i - v3i;
    xr[0] = E0r + O0r; xi[0] = E0i + O0i;
    xr[4] = E0r - O0r; xi[4] = E0i - O0i;
    float p1r = c * (O1r + sg * O1i), p1i = c * (O1i - sg * O1r);   // W8^1 * O1
    xr[1] = E1r + p1r; xi[1] = E1i + p1i;
    xr[5] = E1r - p1r; xi[5] = E1i - p1i;
    float p2r = sg * O2i, p2i = -sg * O2r;                          // W8^2 * O2
    xr[2] = E2r + p2r; xi[2] = E2i + p2i;
    xr[6] = E2r - p2r; xi[6] = E2i - p2i;
    float p3r = c * (sg * O3i - O3r), p3i = -c * (O3i + sg * O3r);  // W8^3 * O3
    xr[3] = E3r + p3r; xi[3] = E3i + p3i;
    xr[7] = E3r - p3r; xi[7] = E3i - p3i;
}

DI void dft16(float* xr, float* xi, float sg) {
    const float C16[8] = {1.f, 0.92387953251128674f, 0.70710678118654752f, 0.38268343236508977f,
                          0.f, -0.38268343236508977f, -0.70710678118654752f, -0.92387953251128674f};
    const float S16[8] = {0.f, 0.38268343236508977f, 0.70710678118654752f, 0.92387953251128674f,
                          1.f, 0.92387953251128674f, 0.70710678118654752f, 0.38268343236508977f};
    float er[8], ei[8], orr[8], oii[8];
    #pragma unroll
    for (int j = 0; j < 8; j++) {
        er[j] = xr[2 * j];     ei[j] = xi[2 * j];
        orr[j] = xr[2 * j + 1]; oii[j] = xi[2 * j + 1];
    }
    dft8(er, ei, sg);
    dft8(orr, oii, sg);
    #pragma unroll
    for (int k = 0; k < 8; k++) {
        float wr = C16[k], wi = -S16[k] * sg;
        float pr = wr * orr[k] - wi * oii[k];
        float pi = wr * oii[k] + wi * orr[k];
        xr[k]     = er[k] + pr; xi[k]     = ei[k] + pi;
        xr[k + 8] = er[k] - pr; xi[k + 8] = ei[k] - pi;
    }
}

// ---------------- Stockham stages ----------------
// y[q + s*(r*p + k)] = sum_j x[q + s*(p + m*j)] * Wr^{jk} * Wn^{pk};  base q+s*p == g
template <int NN, int SS>
DI void stage8(const float* sr, const float* si, float* dr, float* di, float sg) {
    constexpr int M = NN / 8;
    constexpr int STEP = NFFT / NN;
    for (int g = threadIdx.x; g < M * SS; g += 256) {
        int p = g / SS;
        int q = g - p * SS;
        float ar[8], ai[8];
        #pragma unroll
        for (int j = 0; j < 8; j++) {
            ar[j] = sr[g + SS * M * j];
            ai[j] = si[g + SS * M * j];
        }
        dft8(ar, ai, sg);
        int ob = q + SS * 8 * p;
        #pragma unroll
        for (int k = 0; k < 8; k++) {
            int tix = (STEP * p * k) & (NFFT - 1);
            float2 w = g_tw[tix];
            float wi = w.y * sg;
            dr[ob + SS * k] = ar[k] * w.x - ai[k] * wi;
            di[ob + SS * k] = ar[k] * wi + ai[k] * w.x;
        }
    }
}

DI void stage16_final(const float* sr, const float* si, float* dr, float* di, float sg) {
    for (int g = threadIdx.x; g < 512; g += 256) {
        float ar[16], ai[16];
        #pragma unroll
        for (int j = 0; j < 16; j++) {
            ar[j] = sr[g + 512 * j];
            ai[j] = si[g + 512 * j];
        }
        dft16(ar, ai, sg);
        #pragma unroll
        for (int k = 0; k < 16; k++) {
            dr[g + 512 * k] = ar[k];
            di[g + 512 * k] = ai[k];
        }
    }
}

// full 8192-pt complex FFT over smem SoA; result lands in (r0, i0), natural order
DI void fft8192(float* r0, float* i0, float* r1, float* i1, float sg) {
    stage8<8192, 1>(r0, i0, r1, i1, sg);  __syncthreads();
    stage8<1024, 8>(r1, i1, r0, i0, sg);  __syncthreads();
    stage8<128, 64>(r0, i0, r1, i1, sg);  __syncthreads();
    stage16_final(r1, i1, r0, i0, sg);    __syncthreads();
}

// ---------------- kernels ----------------
__global__ void __launch_bounds__(256) twiddle_kernel() {
    int t = blockIdx.x * 256 + threadIdx.x;
    double s, c;
    sincos(2.0 * 3.14159265358979323846 * (double)t / (double)NFFT, &s, &c);
    g_tw[t] = make_float2((float)c, (float)(-s));
}

__global__ void __launch_bounds__(256) hfft_kernel(const float* __restrict__ ir) {
    extern __shared__ float sm[];
    float *r0 = sm, *i0 = sm + NFFT, *r1 = sm + 2 * NFFT, *i1 = sm + 3 * NFFT;
    const int p = blockIdx.x;
    for (int j = threadIdx.x; j < NFFT; j += 256) {
        int idx = p * HOP + j;
        r0[j] = (j < HOP && idx < L) ? ir[idx] : 0.f;
        i0[j] = 0.f;
    }
    __syncthreads();
    fft8192(r0, i0, r1, i1, 1.f);
    const float inv = 1.f / (float)NFFT;
    float2* dst = g_H + (size_t)p * NFFT;
    for (int k = threadIdx.x; k < NFFT; k += 256)
        dst[k] = make_float2(r0[k] * inv, i0[k] * inv);
}

__global__ void __launch_bounds__(256) fwd_kernel(const float* __restrict__ x) {
    extern __shared__ float sm[];
    float *r0 = sm, *i0 = sm + NFFT, *r1 = sm + 2 * NFFT, *i1 = sm + 3 * NFFT;
    const int b = blockIdx.x;
    const int pair = b / NBLK;
    const int t = b - pair * NBLK;
    const float* x0 = x + (size_t)(2 * pair) * T;
    const float* x1 = x + (size_t)(2 * pair + 1) * T;
    const int off = (t - 1) * HOP;
    for (int j = threadIdx.x; j < NFFT; j += 256) {
        int n = off + j;
        bool ok = (n >= 0) && (n < T);
        r0[j] = ok ? x0[n] : 0.f;
        i0[j] = ok ? x1[n] : 0.f;
    }
    __syncthreads();
    fft8192(r0, i0, r1, i1, 1.f);
    float2* dst = g_spec + (size_t)b * NFFT;
    for (int k = threadIdx.x; k < NFFT; k += 256)
        dst[k] = make_float2(r0[k], i0[k]);
}

__global__ void __launch_bounds__(256) out_kernel(const float* __restrict__ x,
                                                  const float* __restrict__ wetp,
                                                  float* __restrict__ out) {
    extern __shared__ float sm[];
    float *r0 = sm, *i0 = sm + NFFT, *r1 = sm + 2 * NFFT, *i1 = sm + 3 * NFFT;
    const int b = blockIdx.x;
    const int pair = b / NBLK;
    const int t = b - pair * NBLK;
    const int tid = threadIdx.x;

    // ---- accumulate acc[k] = sum_p X[t-p][k] * H[p][k]  (float4 = 2 complex) ----
    float4 acc[16];
    #pragma unroll
    for (int i = 0; i < 16; i++) acc[i] = make_float4(0.f, 0.f, 0.f, 0.f);

    for (int p = 0; p < NP; p++) {
        int s = t - p;
        if (s < 0) break;
        const float4* X4 = (const float4*)(g_spec + (size_t)(pair * NBLK + s) * NFFT);
        const float4* H4 = (const float4*)(g_H + (size_t)p * NFFT);
        #pragma unroll 4
        for (int i = 0; i < 16; i++) {
            int f = tid + 256 * i;
            float4 xv = X4[f];
            float4 hv = H4[f];
            acc[i].x += xv.x * hv.x - xv.y * hv.y;
            acc[i].y += xv.x * hv.y + xv.y * hv.x;
            acc[i].z += xv.z * hv.z - xv.w * hv.w;
            acc[i].w += xv.z * hv.w + xv.w * hv.z;
        }
    }
    #pragma unroll
    for (int i = 0; i < 16; i++) {
        int f = tid + 256 * i;
        r0[2 * f]     = acc[i].x;  i0[2 * f]     = acc[i].y;
        r0[2 * f + 1] = acc[i].z;  i0[2 * f + 1] = acc[i].w;
    }
    __syncthreads();

    // ---- unnormalized inverse FFT (H prescaled by 1/N) ----
    fft8192(r0, i0, r1, i1, -1.f);

    // ---- fused wet/dry store: valid samples are second half j in [HOP, NFFT) ----
    const float wet = 1.f / (1.f + __expf(-wetp[0]));
    const float dry = 1.f - wet;
    const float* x0 = x + (size_t)(2 * pair) * T;
    const float* x1 = x + (size_t)(2 * pair + 1) * T;
    float* o0 = out + (size_t)(2 * pair) * T;
    float* o1 = out + (size_t)(2 * pair + 1) * T;
    for (int u = tid; u < HOP; u += 256) {
        int n = t * HOP + u;
        if (n < T) {
            int j = HOP + u;
            o0[n] = dry * x0[n] + wet * r0[j];
            o1[n] = dry * x1[n] + wet * i0[j];
        }
    }
}

// ---------------- launch ----------------
extern "C" void kernel_launch(void* const* d_in, const int* in_sizes, int n_in,
                              void* d_out, int out_size) {
    const float* x    = (const float*)d_in[0];
    const float* ir   = (const float*)d_in[1];
    const float* wetp = (const float*)d_in[2];
    float* out        = (float*)d_out;

    cudaFuncSetAttribute(hfft_kernel, cudaFuncAttributeMaxDynamicSharedMemorySize, SMEMB);
    cudaFuncSetAttribute(fwd_kernel, cudaFuncAttributeMaxDynamicSharedMemorySize, SMEMB);
    cudaFuncSetAttribute(out_kernel, cudaFuncAttributeMaxDynamicSharedMemorySize, SMEMB);

    twiddle_kernel<<<NFFT / 256, 256>>>();
    hfft_kernel<<<NP, 256, SMEMB>>>(ir);
    fwd_kernel<<<NPAIR * NBLK, 256, SMEMB>>>(x);
    out_kernel<<<NPAIR * NBLK, 256, SMEMB>>>(x, wetp, out);
}

// round 7
// speedup vs baseline: 6.4740x; 1.3693x over previous
#include <cuda_runtime.h>
#include <cstdint>
#include <math.h>

#define DI __device__ __forceinline__

// ---------------- problem constants ----------------
constexpr int T     = 441000;
constexpr int L     = 44100;
constexpr int BATCH = 32;
constexpr int NFFT  = 8192;
constexpr int HOP   = 4096;
constexpr int NBLK  = 108;              // ceil(T / HOP)
constexpr int NP    = 11;               // ceil(L / HOP) IR partitions
constexpr int NPAIR = BATCH / 2;        // 16 complex-packed row pairs
constexpr int NTH   = 512;              // threads per FFT CTA (16 warps)

constexpr int SMEMB = 4 * NFFT * 4;     // 131072 B: re0,im0,re1,im1

// ---------------- global scratch ----------------
__device__ float2 g_spec[(size_t)NPAIR * NBLK * NFFT];  // 108 MB
__device__ float2 g_H[(size_t)NP * NFFT];               // 704 KB (prescaled by 1/NFFT)
__device__ float2 g_tw[NFFT];                           // e^{-2pi i t / NFFT}

// ---------------- register DFTs (sign sg=+1 fwd e^{-}, sg=-1 inv e^{+}) ----
DI void dft8(float* xr, float* xi, float sg) {
    const float c = 0.70710678118654752f;
    float t0r = xr[0] + xr[4], t0i = xi[0] + xi[4];
    float t1r = xr[0] - xr[4], t1i = xi[0] - xi[4];
    float t2r = xr[2] + xr[6], t2i = xi[2] + xi[6];
    float t3r = xr[2] - xr[6], t3i = xi[2] - xi[6];
    float w3r = sg * t3i, w3i = -sg * t3r;              // W4 * t3
    float E0r = t0r + t2r, E0i = t0i + t2i;
    float E1r = t1r + w3r, E1i = t1i + w3i;
    float E2r = t0r - t2r, E2i = t0i - t2i;
    float E3r = t1r - w3r, E3i = t1i - w3i;
    float u0r = xr[1] + xr[5], u0i = xi[1] + xi[5];
    float u1r = xr[1] - xr[5], u1i = xi[1] - xi[5];
    float u2r = xr[3] + xr[7], u2i = xi[3] + xi[7];
    float u3r = xr[3] - xr[7], u3i = xi[3] - xi[7];
    float v3r = sg * u3i, v3i = -sg * u3r;
    float O0r = u0r + u2r, O0i = u0i + u2i;
    float O1r = u1r + v3r, O1i = u1i + v3i;
    float O2r = u0r - u2r, O2i = u0i - u2i;
    float O3r = u1r - v3r, O3i = u1i - v3i;
    xr[0] = E0r + O0r; xi[0] = E0i + O0i;
    xr[4] = E0r - O0r; xi[4] = E0i - O0i;
    float p1r = c * (O1r + sg * O1i), p1i = c * (O1i - sg * O1r);   // W8^1 * O1
    xr[1] = E1r + p1r; xi[1] = E1i + p1i;
    xr[5] = E1r - p1r; xi[5] = E1i - p1i;
    float p2r = sg * O2i, p2i = -sg * O2r;                          // W8^2 * O2
    xr[2] = E2r + p2r; xi[2] = E2i + p2i;
    xr[6] = E2r - p2r; xi[6] = E2i - p2i;
    float p3r = c * (sg * O3i - O3r), p3i = -c * (O3i + sg * O3r);  // W8^3 * O3
    xr[3] = E3r + p3r; xi[3] = E3i + p3i;
    xr[7] = E3r - p3r; xi[7] = E3i - p3i;
}

DI void dft16(float* xr, float* xi, float sg) {
    const float C16[8] = {1.f, 0.92387953251128674f, 0.70710678118654752f, 0.38268343236508977f,
                          0.f, -0.38268343236508977f, -0.70710678118654752f, -0.92387953251128674f};
    const float S16[8] = {0.f, 0.38268343236508977f, 0.70710678118654752f, 0.92387953251128674f,
                          1.f, 0.92387953251128674f, 0.70710678118654752f, 0.38268343236508977f};
    float er[8], ei[8], orr[8], oii[8];
    #pragma unroll
    for (int j = 0; j < 8; j++) {
        er[j] = xr[2 * j];     ei[j] = xi[2 * j];
        orr[j] = xr[2 * j + 1]; oii[j] = xi[2 * j + 1];
    }
    dft8(er, ei, sg);
    dft8(orr, oii, sg);
    #pragma unroll
    for (int k = 0; k < 8; k++) {
        float wr = C16[k], wi = -S16[k] * sg;
        float pr = wr * orr[k] - wi * oii[k];
        float pi = wr * oii[k] + wi * orr[k];
        xr[k]     = er[k] + pr; xi[k]     = ei[k] + pi;
        xr[k + 8] = er[k] - pr; xi[k + 8] = ei[k] - pi;
    }
}

// ---------------- Stockham stages ----------------
template <int NN, int SS>
DI void stage8(const float* sr, const float* si, float* dr, float* di, float sg) {
    constexpr int M = NN / 8;
    constexpr int STEP = NFFT / NN;
    for (int g = threadIdx.x; g < M * SS; g += NTH) {
        int p = g / SS;
        int q = g - p * SS;
        float ar[8], ai[8];
        #pragma unroll
        for (int j = 0; j < 8; j++) {
            ar[j] = sr[g + SS * M * j];
            ai[j] = si[g + SS * M * j];
        }
        dft8(ar, ai, sg);
        int ob = q + SS * 8 * p;
        #pragma unroll
        for (int k = 0; k < 8; k++) {
            int tix = (STEP * p * k) & (NFFT - 1);
            float2 w = g_tw[tix];
            float wi = w.y * sg;
            dr[ob + SS * k] = ar[k] * w.x - ai[k] * wi;
            di[ob + SS * k] = ar[k] * wi + ai[k] * w.x;
        }
    }
}

DI void stage16_final(const float* sr, const float* si, float* dr, float* di, float sg) {
    for (int g = threadIdx.x; g < 512; g += NTH) {
        float ar[16], ai[16];
        #pragma unroll
        for (int j = 0; j < 16; j++) {
            ar[j] = sr[g + 512 * j];
            ai[j] = si[g + 512 * j];
        }
        dft16(ar, ai, sg);
        #pragma unroll
        for (int k = 0; k < 16; k++) {
            dr[g + 512 * k] = ar[k];
            di[g + 512 * k] = ai[k];
        }
    }
}

// full 8192-pt complex FFT over smem SoA; result lands in (r0, i0), natural order
DI void fft8192(float* r0, float* i0, float* r1, float* i1, float sg) {
    stage8<8192, 1>(r0, i0, r1, i1, sg);  __syncthreads();
    stage8<1024, 8>(r1, i1, r0, i0, sg);  __syncthreads();
    stage8<128, 64>(r0, i0, r1, i1, sg);  __syncthreads();
    stage16_final(r1, i1, r0, i0, sg);    __syncthreads();
}

// ---------------- kernels ----------------
__global__ void __launch_bounds__(256) twiddle_kernel() {
    int t = blockIdx.x * 256 + threadIdx.x;
    double s, c;
    sincos(2.0 * 3.14159265358979323846 * (double)t / (double)NFFT, &s, &c);
    g_tw[t] = make_float2((float)c, (float)(-s));
}

__global__ void __launch_bounds__(NTH) hfft_kernel(const float* __restrict__ ir) {
    extern __shared__ float sm[];
    float *r0 = sm, *i0 = sm + NFFT, *r1 = sm + 2 * NFFT, *i1 = sm + 3 * NFFT;
    const int p = blockIdx.x;
    for (int j = threadIdx.x; j < NFFT; j += NTH) {
        int idx = p * HOP + j;
        r0[j] = (j < HOP && idx < L) ? ir[idx] : 0.f;
        i0[j] = 0.f;
    }
    __syncthreads();
    fft8192(r0, i0, r1, i1, 1.f);
    const float inv = 1.f / (float)NFFT;
    float2* dst = g_H + (size_t)p * NFFT;
    for (int k = threadIdx.x; k < NFFT; k += NTH)
        dst[k] = make_float2(r0[k] * inv, i0[k] * inv);
}

__global__ void __launch_bounds__(NTH) fwd_kernel(const float* __restrict__ x) {
    extern __shared__ float sm[];
    float *r0 = sm, *i0 = sm + NFFT, *r1 = sm + 2 * NFFT, *i1 = sm + 3 * NFFT;
    const int b = blockIdx.x;
    const int pair = b / NBLK;
    const int t = b - pair * NBLK;
    const float* x0 = x + (size_t)(2 * pair) * T;
    const float* x1 = x + (size_t)(2 * pair + 1) * T;
    const int off = (t - 1) * HOP;
    for (int j = threadIdx.x; j < NFFT; j += NTH) {
        int n = off + j;
        bool ok = (n >= 0) && (n < T);
        r0[j] = ok ? x0[n] : 0.f;
        i0[j] = ok ? x1[n] : 0.f;
    }
    __syncthreads();
    fft8192(r0, i0, r1, i1, 1.f);
    float2* dst = g_spec + (size_t)b * NFFT;
    for (int k = threadIdx.x; k < NFFT; k += NTH)
        dst[k] = make_float2(r0[k], i0[k]);
}

__global__ void __launch_bounds__(NTH) out_kernel(const float* __restrict__ x,
                                                  const float* __restrict__ wetp,
                                                  float* __restrict__ out) {
    extern __shared__ float sm[];
    float *r0 = sm, *i0 = sm + NFFT, *r1 = sm + 2 * NFFT, *i1 = sm + 3 * NFFT;
    const int b = blockIdx.x;
    const int pair = b / NBLK;
    const int t = b - pair * NBLK;
    const int tid = threadIdx.x;

    // ---- accumulate acc[k] = sum_p X[t-p][k] * H[p][k]  (float4 = 2 complex) ----
    float4 acc[8];
    #pragma unroll
    for (int i = 0; i < 8; i++) acc[i] = make_float4(0.f, 0.f, 0.f, 0.f);

    for (int p = 0; p < NP; p++) {
        int s = t - p;
        if (s < 0) break;
        const float4* X4 = (const float4*)(g_spec + (size_t)(pair * NBLK + s) * NFFT);
        const float4* H4 = (const float4*)(g_H + (size_t)p * NFFT);
        #pragma unroll
        for (int i = 0; i < 8; i++) {
            int f = tid + NTH * i;
            float4 xv = X4[f];
            float4 hv = H4[f];
            acc[i].x += xv.x * hv.x - xv.y * hv.y;
            acc[i].y += xv.x * hv.y + xv.y * hv.x;
            acc[i].z += xv.z * hv.z - xv.w * hv.w;
            acc[i].w += xv.z * hv.w + xv.w * hv.z;
        }
    }
    #pragma unroll
    for (int i = 0; i < 8; i++) {
        int f = tid + NTH * i;
        r0[2 * f]     = acc[i].x;  i0[2 * f]     = acc[i].y;
        r0[2 * f + 1] = acc[i].z;  i0[2 * f + 1] = acc[i].w;
    }
    __syncthreads();

    // ---- unnormalized inverse FFT (H prescaled by 1/N) ----
    fft8192(r0, i0, r1, i1, -1.f);

    // ---- fused wet/dry store: valid samples are second half j in [HOP, NFFT) ----
    const float wet = 1.f / (1.f + __expf(-wetp[0]));
    const float dry = 1.f - wet;
    const float* x0 = x + (size_t)(2 * pair) * T;
    const float* x1 = x + (size_t)(2 * pair + 1) * T;
    float* o0 = out + (size_t)(2 * pair) * T;
    float* o1 = out + (size_t)(2 * pair + 1) * T;
    for (int u = tid; u < HOP; u += NTH) {
        int n = t * HOP + u;
        if (n < T) {
            int j = HOP + u;
            o0[n] = dry * x0[n] + wet * r0[j];
            o1[n] = dry * x1[n] + wet * i0[j];
        }
    }
}

// ---------------- launch ----------------
extern "C" void kernel_launch(void* const* d_in, const int* in_sizes, int n_in,
                              void* d_out, int out_size) {
    const float* x    = (const float*)d_in[0];
    const float* ir   = (const float*)d_in[1];
    const float* wetp = (const float*)d_in[2];
    float* out        = (float*)d_out;

    cudaFuncSetAttribute(hfft_kernel, cudaFuncAttributeMaxDynamicSharedMemorySize, SMEMB);
    cudaFuncSetAttribute(fwd_kernel, cudaFuncAttributeMaxDynamicSharedMemorySize, SMEMB);
    cudaFuncSetAttribute(out_kernel, cudaFuncAttributeMaxDynamicSharedMemorySize, SMEMB);

    twiddle_kernel<<<NFFT / 256, 256>>>();
    hfft_kernel<<<NP, NTH, SMEMB>>>(ir);
    fwd_kernel<<<NPAIR * NBLK, NTH, SMEMB>>>(x);
    out_kernel<<<NPAIR * NBLK, NTH, SMEMB>>>(x, wetp, out);
}

// round 8
// speedup vs baseline: 10.8487x; 1.6757x over previous
#include <cuda_runtime.h>
#include <cstdint>
#include <math.h>

#define DI __device__ __forceinline__

// ---------------- problem constants ----------------
constexpr int T     = 441000;
constexpr int L     = 44100;
constexpr int BATCH = 32;
constexpr int NFFT  = 8192;
constexpr int HOP   = 4096;
constexpr int NBLK  = 108;              // ceil(T / HOP)
constexpr int NP    = 11;               // ceil(L / HOP) IR partitions
constexpr int NPAIR = BATCH / 2;        // 16 complex-packed row pairs
constexpr int NTH   = 512;              // threads per FFT CTA (16 warps)

constexpr int SMEMB = NFFT * 8;         // 65536 B: single float2 buffer (in-place FFT)

// ---------------- global scratch ----------------
__device__ float2 g_spec[(size_t)NPAIR * NBLK * NFFT];  // 108 MB
__device__ float2 g_H[(size_t)NP * NFFT];               // 704 KB (prescaled by 1/NFFT)
__device__ float2 g_tw[NFFT];                           // e^{-2pi i t / NFFT}

// swizzle on float2 index: kills write bank conflicts, preserves read patterns
DI int SWZ(int a) { return a ^ ((a >> 4) & 15); }

// ---------------- register DFTs (sign sg=+1 fwd e^{-}, sg=-1 inv e^{+}) ----
DI void dft8(float* xr, float* xi, float sg) {
    const float c = 0.70710678118654752f;
    float t0r = xr[0] + xr[4], t0i = xi[0] + xi[4];
    float t1r = xr[0] - xr[4], t1i = xi[0] - xi[4];
    float t2r = xr[2] + xr[6], t2i = xi[2] + xi[6];
    float t3r = xr[2] - xr[6], t3i = xi[2] - xi[6];
    float w3r = sg * t3i, w3i = -sg * t3r;              // W4 * t3
    float E0r = t0r + t2r, E0i = t0i + t2i;
    float E1r = t1r + w3r, E1i = t1i + w3i;
    float E2r = t0r - t2r, E2i = t0i - t2i;
    float E3r = t1r - w3r, E3i = t1i - w3i;
    float u0r = xr[1] + xr[5], u0i = xi[1] + xi[5];
    float u1r = xr[1] - xr[5], u1i = xi[1] - xi[5];
    float u2r = xr[3] + xr[7], u2i = xi[3] + xi[7];
    float u3r = xr[3] - xr[7], u3i = xi[3] - xi[7];
    float v3r = sg * u3i, v3i = -sg * u3r;
    float O0r = u0r + u2r, O0i = u0i + u2i;
    float O1r = u1r + v3r, O1i = u1i + v3i;
    float O2r = u0r - u2r, O2i = u0i - u2i;
    float O3r = u1r - v3r, O3i = u1i - v3i;
    xr[0] = E0r + O0r; xi[0] = E0i + O0i;
    xr[4] = E0r - O0r; xi[4] = E0i - O0i;
    float p1r = c * (O1r + sg * O1i), p1i = c * (O1i - sg * O1r);   // W8^1 * O1
    xr[1] = E1r + p1r; xi[1] = E1i + p1i;
    xr[5] = E1r - p1r; xi[5] = E1i - p1i;
    float p2r = sg * O2i, p2i = -sg * O2r;                          // W8^2 * O2
    xr[2] = E2r + p2r; xi[2] = E2i + p2i;
    xr[6] = E2r - p2r; xi[6] = E2i - p2i;
    float p3r = c * (sg * O3i - O3r), p3i = -c * (O3i + sg * O3r);  // W8^3 * O3
    xr[3] = E3r + p3r; xi[3] = E3i + p3i;
    xr[7] = E3r - p3r; xi[7] = E3i - p3i;
}

DI void dft16(float* xr, float* xi, float sg) {
    const float C16[8] = {1.f, 0.92387953251128674f, 0.70710678118654752f, 0.38268343236508977f,
                          0.f, -0.38268343236508977f, -0.70710678118654752f, -0.92387953251128674f};
    const float S16[8] = {0.f, 0.38268343236508977f, 0.70710678118654752f, 0.92387953251128674f,
                          1.f, 0.92387953251128674f, 0.70710678118654752f, 0.38268343236508977f};
    float er[8], ei[8], orr[8], oii[8];
    #pragma unroll
    for (int j = 0; j < 8; j++) {
        er[j] = xr[2 * j];     ei[j] = xi[2 * j];
        orr[j] = xr[2 * j + 1]; oii[j] = xi[2 * j + 1];
    }
    dft8(er, ei, sg);
    dft8(orr, oii, sg);
    #pragma unroll
    for (int k = 0; k < 8; k++) {
        float wr = C16[k], wi = -S16[k] * sg;
        float pr = wr * orr[k] - wi * oii[k];
        float pi = wr * oii[k] + wi * orr[k];
        xr[k]     = er[k] + pr; xi[k]     = ei[k] + pi;
        xr[k + 8] = er[k] - pr; xi[k + 8] = ei[k] - pi;
    }
}

// ---------------- in-place Stockham stages (single float2 buffer) --------
// All stages read at {g + 1024*j}; read-all -> sync -> write-all -> sync.
template <int SS, int STEP>
DI void stage8_ip(float2* s, float sg) {
    float ar[2][8], ai[2][8];
    const int g0 = threadIdx.x;
    #pragma unroll
    for (int h = 0; h < 2; h++) {
        const int g = g0 + 512 * h;
        #pragma unroll
        for (int j = 0; j < 8; j++) {
            float2 v = s[SWZ(g + 1024 * j)];
            ar[h][j] = v.x; ai[h][j] = v.y;
        }
    }
    __syncthreads();
    #pragma unroll
    for (int h = 0; h < 2; h++) {
        const int g = g0 + 512 * h;
        const int p = g / SS;
        const int q = g - p * SS;
        dft8(ar[h], ai[h], sg);
        const int ob = q + SS * 8 * p;
        #pragma unroll
        for (int k = 0; k < 8; k++) {
            int tix = (STEP * p * k) & (NFFT - 1);
            float2 w = g_tw[tix];
            float wi = w.y * sg;
            s[SWZ(ob + SS * k)] = make_float2(ar[h][k] * w.x - ai[h][k] * wi,
                                              ar[h][k] * wi + ai[h][k] * w.x);
        }
    }
    __syncthreads();
}

DI void stage16_ip(float2* s, float sg) {
    float ar[16], ai[16];
    const int g = threadIdx.x;
    #pragma unroll
    for (int j = 0; j < 16; j++) {
        float2 v = s[SWZ(g + 512 * j)];
        ar[j] = v.x; ai[j] = v.y;
    }
    __syncthreads();
    dft16(ar, ai, sg);
    #pragma unroll
    for (int k = 0; k < 16; k++)
        s[SWZ(g + 512 * k)] = make_float2(ar[k], ai[k]);
    __syncthreads();
}

// full 8192-pt complex FFT in-place over swizzled smem; natural order result.
// caller must __syncthreads() after staging inputs.
DI void fft8192_ip(float2* s, float sg) {
    stage8_ip<1, 1>(s, sg);
    stage8_ip<8, 8>(s, sg);
    stage8_ip<64, 64>(s, sg);
    stage16_ip(s, sg);
}

// ---------------- kernels ----------------
__global__ void __launch_bounds__(256) twiddle_kernel() {
    int t = blockIdx.x * 256 + threadIdx.x;
    double s, c;
    sincos(2.0 * 3.14159265358979323846 * (double)t / (double)NFFT, &s, &c);
    g_tw[t] = make_float2((float)c, (float)(-s));
}

__global__ void __launch_bounds__(NTH, 2) hfft_kernel(const float* __restrict__ ir) {
    extern __shared__ float2 sm[];
    const int p = blockIdx.x;
    for (int j = threadIdx.x; j < NFFT; j += NTH) {
        int idx = p * HOP + j;
        float v = (j < HOP && idx < L) ? ir[idx] : 0.f;
        sm[SWZ(j)] = make_float2(v, 0.f);
    }
    __syncthreads();
    fft8192_ip(sm, 1.f);
    const float inv = 1.f / (float)NFFT;
    float2* dst = g_H + (size_t)p * NFFT;
    for (int k = threadIdx.x; k < NFFT; k += NTH) {
        float2 v = sm[SWZ(k)];
        dst[k] = make_float2(v.x * inv, v.y * inv);
    }
}

__global__ void __launch_bounds__(NTH, 2) fwd_kernel(const float* __restrict__ x) {
    extern __shared__ float2 sm[];
    const int b = blockIdx.x;
    const int pair = b / NBLK;
    const int t = b - pair * NBLK;
    const float* x0 = x + (size_t)(2 * pair) * T;
    const float* x1 = x + (size_t)(2 * pair + 1) * T;
    const int off = (t - 1) * HOP;
    for (int j = threadIdx.x; j < NFFT; j += NTH) {
        int n = off + j;
        bool ok = (n >= 0) && (n < T);
        sm[SWZ(j)] = make_float2(ok ? x0[n] : 0.f, ok ? x1[n] : 0.f);
    }
    __syncthreads();
    fft8192_ip(sm, 1.f);
    float2* dst = g_spec + (size_t)b * NFFT;
    for (int k = threadIdx.x; k < NFFT; k += NTH)
        dst[k] = sm[SWZ(k)];
}

__global__ void __launch_bounds__(NTH, 2) out_kernel(const float* __restrict__ x,
                                                     const float* __restrict__ wetp,
                                                     float* __restrict__ out) {
    extern __shared__ float2 sm[];
    const int b = blockIdx.x;
    const int pair = b / NBLK;
    const int t = b - pair * NBLK;
    const int tid = threadIdx.x;

    // ---- accumulate acc[k] = sum_p X[t-p][k] * H[p][k]  (float4 = 2 complex) ----
    float4 acc[8];
    #pragma unroll
    for (int i = 0; i < 8; i++) acc[i] = make_float4(0.f, 0.f, 0.f, 0.f);

    for (int p = 0; p < NP; p++) {
        int s = t - p;
        if (s < 0) break;
        const float4* X4 = (const float4*)(g_spec + (size_t)(pair * NBLK + s) * NFFT);
        const float4* H4 = (const float4*)(g_H + (size_t)p * NFFT);
        #pragma unroll
        for (int i = 0; i < 8; i++) {
            int f = tid + NTH * i;
            float4 xv = X4[f];
            float4 hv = H4[f];
            acc[i].x += xv.x * hv.x - xv.y * hv.y;
            acc[i].y += xv.x * hv.y + xv.y * hv.x;
            acc[i].z += xv.z * hv.z - xv.w * hv.w;
            acc[i].w += xv.z * hv.w + xv.w * hv.z;
        }
    }
    #pragma unroll
    for (int i = 0; i < 8; i++) {
        int f = tid + NTH * i;
        sm[SWZ(2 * f)]     = make_float2(acc[i].x, acc[i].y);
        sm[SWZ(2 * f + 1)] = make_float2(acc[i].z, acc[i].w);
    }
    __syncthreads();

    // ---- unnormalized inverse FFT (H prescaled by 1/N) ----
    fft8192_ip(sm, -1.f);

    // ---- fused wet/dry store: valid samples are second half j in [HOP, NFFT) ----
    const float wet = 1.f / (1.f + __expf(-wetp[0]));
    const float dry = 1.f - wet;
    const float* x0 = x + (size_t)(2 * pair) * T;
    const float* x1 = x + (size_t)(2 * pair + 1) * T;
    float* o0 = out + (size_t)(2 * pair) * T;
    float* o1 = out + (size_t)(2 * pair + 1) * T;
    for (int u = tid; u < HOP; u += NTH) {
        int n = t * HOP + u;
        if (n < T) {
            float2 y = sm[SWZ(HOP + u)];
            o0[n] = dry * x0[n] + wet * y.x;
            o1[n] = dry * x1[n] + wet * y.y;
        }
    }
}

// ---------------- launch ----------------
extern "C" void kernel_launch(void* const* d_in, const int* in_sizes, int n_in,
                              void* d_out, int out_size) {
    const float* x    = (const float*)d_in[0];
    const float* ir   = (const float*)d_in[1];
    const float* wetp = (const float*)d_in[2];
    float* out        = (float*)d_out;

    cudaFuncSetAttribute(hfft_kernel, cudaFuncAttributeMaxDynamicSharedMemorySize, SMEMB);
    cudaFuncSetAttribute(fwd_kernel, cudaFuncAttributeMaxDynamicSharedMemorySize, SMEMB);
    cudaFuncSetAttribute(out_kernel, cudaFuncAttributeMaxDynamicSharedMemorySize, SMEMB);

    twiddle_kernel<<<NFFT / 256, 256>>>();
    hfft_kernel<<<NP, NTH, SMEMB>>>(ir);
    fwd_kernel<<<NPAIR * NBLK, NTH, SMEMB>>>(x);
    out_kernel<<<NPAIR * NBLK, NTH, SMEMB>>>(x, wetp, out);
}

// round 9
// speedup vs baseline: 14.1974x; 1.3087x over previous
#include <cuda_runtime.h>
#include <cuda_fp16.h>
#include <cstdint>
#include <math.h>

#define DI __device__ __forceinline__

// ---------------- problem constants ----------------
constexpr int T     = 441000;
constexpr int L     = 44100;
constexpr int BATCH = 32;
constexpr int NFFT  = 8192;
constexpr int HOP   = 4096;
constexpr int NBLK  = 108;              // ceil(T / HOP)
constexpr int NP    = 11;               // ceil(L / HOP) IR partitions
constexpr int NPAIR = BATCH / 2;        // 16 complex-packed row pairs
constexpr int NTH   = 512;              // threads per FFT CTA (16 warps)

constexpr int SMEMB = NFFT * 8;         // 65536 B: single float2 buffer (in-place FFT)

// ---------------- global scratch ----------------
// spectra stored as half2 (re, im) to halve L2/DRAM traffic; math stays fp32
__device__ __align__(128) __half2 g_spec[(size_t)NPAIR * NBLK * NFFT];  // 54 MB
__device__ __align__(128) __half2 g_H[(size_t)NP * NFFT];               // 352 KB (prescaled 1/NFFT)
__device__ float2 g_tw[NFFT];                                           // e^{-2pi i t / NFFT}

// swizzle on float2 index: kills write bank conflicts, preserves read patterns
DI int SWZ(int a) { return a ^ ((a >> 4) & 15); }

// ---------------- register DFTs (sign sg=+1 fwd e^{-}, sg=-1 inv e^{+}) ----
DI void dft8(float* xr, float* xi, float sg) {
    const float c = 0.70710678118654752f;
    float t0r = xr[0] + xr[4], t0i = xi[0] + xi[4];
    float t1r = xr[0] - xr[4], t1i = xi[0] - xi[4];
    float t2r = xr[2] + xr[6], t2i = xi[2] + xi[6];
    float t3r = xr[2] - xr[6], t3i = xi[2] - xi[6];
    float w3r = sg * t3i, w3i = -sg * t3r;              // W4 * t3
    float E0r = t0r + t2r, E0i = t0i + t2i;
    float E1r = t1r + w3r, E1i = t1i + w3i;
    float E2r = t0r - t2r, E2i = t0i - t2i;
    float E3r = t1r - w3r, E3i = t1i - w3i;
    float u0r = xr[1] + xr[5], u0i = xi[1] + xi[5];
    float u1r = xr[1] - xr[5], u1i = xi[1] - xi[5];
    float u2r = xr[3] + xr[7], u2i = xi[3] + xi[7];
    float u3r = xr[3] - xr[7], u3i = xi[3] - xi[7];
    float v3r = sg * u3i, v3i = -sg * u3r;
    float O0r = u0r + u2r, O0i = u0i + u2i;
    float O1r = u1r + v3r, O1i = u1i + v3i;
    float O2r = u0r - u2r, O2i = u0i - u2i;
    float O3r = u1r - v3r, O3i = u1i - v3i;
    xr[0] = E0r + O0r; xi[0] = E0i + O0i;
    xr[4] = E0r - O0r; xi[4] = E0i - O0i;
    float p1r = c * (O1r + sg * O1i), p1i = c * (O1i - sg * O1r);   // W8^1 * O1
    xr[1] = E1r + p1r; xi[1] = E1i + p1i;
    xr[5] = E1r - p1r; xi[5] = E1i - p1i;
    float p2r = sg * O2i, p2i = -sg * O2r;                          // W8^2 * O2
    xr[2] = E2r + p2r; xi[2] = E2i + p2i;
    xr[6] = E2r - p2r; xi[6] = E2i - p2i;
    float p3r = c * (sg * O3i - O3r), p3i = -c * (O3i + sg * O3r);  // W8^3 * O3
    xr[3] = E3r + p3r; xi[3] = E3i + p3i;
    xr[7] = E3r - p3r; xi[7] = E3i - p3i;
}

DI void dft16(float* xr, float* xi, float sg) {
    const float C16[8] = {1.f, 0.92387953251128674f, 0.70710678118654752f, 0.38268343236508977f,
                          0.f, -0.38268343236508977f, -0.70710678118654752f, -0.92387953251128674f};
    const float S16[8] = {0.f, 0.38268343236508977f, 0.70710678118654752f, 0.92387953251128674f,
                          1.f, 0.92387953251128674f, 0.70710678118654752f, 0.38268343236508977f};
    float er[8], ei[8], orr[8], oii[8];
    #pragma unroll
    for (int j = 0; j < 8; j++) {
        er[j] = xr[2 * j];     ei[j] = xi[2 * j];
        orr[j] = xr[2 * j + 1]; oii[j] = xi[2 * j + 1];
    }
    dft8(er, ei, sg);
    dft8(orr, oii, sg);
    #pragma unroll
    for (int k = 0; k < 8; k++) {
        float wr = C16[k], wi = -S16[k] * sg;
        float pr = wr * orr[k] - wi * oii[k];
        float pi = wr * oii[k] + wi * orr[k];
        xr[k]     = er[k] + pr; xi[k]     = ei[k] + pi;
        xr[k + 8] = er[k] - pr; xi[k + 8] = ei[k] - pi;
    }
}

// ---------------- in-place Stockham stages (single float2 buffer) --------
template <int SS, int STEP>
DI void stage8_ip(float2* s, float sg) {
    float ar[2][8], ai[2][8];
    const int g0 = threadIdx.x;
    #pragma unroll
    for (int h = 0; h < 2; h++) {
        const int g = g0 + 512 * h;
        #pragma unroll
        for (int j = 0; j < 8; j++) {
            float2 v = s[SWZ(g + 1024 * j)];
            ar[h][j] = v.x; ai[h][j] = v.y;
        }
    }
    __syncthreads();
    #pragma unroll
    for (int h = 0; h < 2; h++) {
        const int g = g0 + 512 * h;
        const int p = g / SS;
        const int q = g - p * SS;
        dft8(ar[h], ai[h], sg);
        const int ob = q + SS * 8 * p;
        #pragma unroll
        for (int k = 0; k < 8; k++) {
            int tix = (STEP * p * k) & (NFFT - 1);
            float2 w = g_tw[tix];
            float wi = w.y * sg;
            s[SWZ(ob + SS * k)] = make_float2(ar[h][k] * w.x - ai[h][k] * wi,
                                              ar[h][k] * wi + ai[h][k] * w.x);
        }
    }
    __syncthreads();
}

DI void stage16_ip(float2* s, float sg) {
    float ar[16], ai[16];
    const int g = threadIdx.x;
    #pragma unroll
    for (int j = 0; j < 16; j++) {
        float2 v = s[SWZ(g + 512 * j)];
        ar[j] = v.x; ai[j] = v.y;
    }
    __syncthreads();
    dft16(ar, ai, sg);
    #pragma unroll
    for (int k = 0; k < 16; k++)
        s[SWZ(g + 512 * k)] = make_float2(ar[k], ai[k]);
    __syncthreads();
}

// full 8192-pt complex FFT in-place over swizzled smem; natural order result.
DI void fft8192_ip(float2* s, float sg) {
    stage8_ip<1, 1>(s, sg);
    stage8_ip<8, 8>(s, sg);
    stage8_ip<64, 64>(s, sg);
    stage16_ip(s, sg);
}

// ---------------- kernels ----------------
__global__ void __launch_bounds__(256) twiddle_kernel() {
    int t = blockIdx.x * 256 + threadIdx.x;
    double s, c;
    sincos(2.0 * 3.14159265358979323846 * (double)t / (double)NFFT, &s, &c);
    g_tw[t] = make_float2((float)c, (float)(-s));
}

__global__ void __launch_bounds__(NTH, 2) hfft_kernel(const float* __restrict__ ir) {
    extern __shared__ float2 sm[];
    const int p = blockIdx.x;
    for (int j = threadIdx.x; j < NFFT; j += NTH) {
        int idx = p * HOP + j;
        float v = (j < HOP && idx < L) ? ir[idx] : 0.f;
        sm[SWZ(j)] = make_float2(v, 0.f);
    }
    __syncthreads();
    fft8192_ip(sm, 1.f);
    const float inv = 1.f / (float)NFFT;
    __half2* dst = g_H + (size_t)p * NFFT;
    for (int k = threadIdx.x; k < NFFT; k += NTH) {
        float2 v = sm[SWZ(k)];
        dst[k] = __floats2half2_rn(v.x * inv, v.y * inv);
    }
}

__global__ void __launch_bounds__(NTH, 2) fwd_kernel(const float* __restrict__ x) {
    extern __shared__ float2 sm[];
    const int b = blockIdx.x;
    const int pair = b / NBLK;
    const int t = b - pair * NBLK;
    const float* x0 = x + (size_t)(2 * pair) * T;
    const float* x1 = x + (size_t)(2 * pair + 1) * T;
    const int off = (t - 1) * HOP;
    for (int j = threadIdx.x; j < NFFT; j += NTH) {
        int n = off + j;
        bool ok = (n >= 0) && (n < T);
        sm[SWZ(j)] = make_float2(ok ? x0[n] : 0.f, ok ? x1[n] : 0.f);
    }
    __syncthreads();
    fft8192_ip(sm, 1.f);
    __half2* dst = g_spec + (size_t)b * NFFT;
    for (int k = threadIdx.x; k < NFFT; k += NTH) {
        float2 v = sm[SWZ(k)];
        dst[k] = __floats2half2_rn(v.x, v.y);
    }
}

// complex MAC of 4 half2 complexes against fp32 accumulators
DI void cmac4(float4& a01, float4& a23, const uint4& xv, const uint4& hv) {
    const __half2* xh = (const __half2*)&xv;
    const __half2* hh = (const __half2*)&hv;
    float2 x0 = __half22float2(xh[0]), h0 = __half22float2(hh[0]);
    float2 x1 = __half22float2(xh[1]), h1 = __half22float2(hh[1]);
    float2 x2 = __half22float2(xh[2]), h2 = __half22float2(hh[2]);
    float2 x3 = __half22float2(xh[3]), h3 = __half22float2(hh[3]);
    a01.x += x0.x * h0.x - x0.y * h0.y;
    a01.y += x0.x * h0.y + x0.y * h0.x;
    a01.z += x1.x * h1.x - x1.y * h1.y;
    a01.w += x1.x * h1.y + x1.y * h1.x;
    a23.x += x2.x * h2.x - x2.y * h2.y;
    a23.y += x2.x * h2.y + x2.y * h2.x;
    a23.z += x3.x * h3.x - x3.y * h3.y;
    a23.w += x3.x * h3.y + x3.y * h3.x;
}

__global__ void __launch_bounds__(NTH, 2) out_kernel(const float* __restrict__ x,
                                                     const float* __restrict__ wetp,
                                                     float* __restrict__ out) {
    extern __shared__ float2 sm[];
    const int b = blockIdx.x;
    const int pair = b / NBLK;
    const int t = b - pair * NBLK;
    const int tid = threadIdx.x;

    // ---- accumulate acc[k] = sum_p X[t-p][k] * H[p][k]  (uint4 = 4 half2 complex) ----
    float4 acc[8];
    #pragma unroll
    for (int i = 0; i < 8; i++) acc[i] = make_float4(0.f, 0.f, 0.f, 0.f);

    for (int p = 0; p < NP; p++) {
        int s = t - p;
        if (s < 0) break;
        const uint4* X4 = (const uint4*)(g_spec + (size_t)(pair * NBLK + s) * NFFT);
        const uint4* H4 = (const uint4*)(g_H + (size_t)p * NFFT);
        #pragma unroll
        for (int i = 0; i < 4; i++) {
            int f = tid + NTH * i;          // quad index: 4 complexes each
            uint4 xv = X4[f];
            uint4 hv = H4[f];
            cmac4(acc[2 * i], acc[2 * i + 1], xv, hv);
        }
    }
    #pragma unroll
    for (int i = 0; i < 4; i++) {
        int base = 4 * (tid + NTH * i);
        sm[SWZ(base + 0)] = make_float2(acc[2 * i].x, acc[2 * i].y);
        sm[SWZ(base + 1)] = make_float2(acc[2 * i].z, acc[2 * i].w);
        sm[SWZ(base + 2)] = make_float2(acc[2 * i + 1].x, acc[2 * i + 1].y);
        sm[SWZ(base + 3)] = make_float2(acc[2 * i + 1].z, acc[2 * i + 1].w);
    }
    __syncthreads();

    // ---- unnormalized inverse FFT (H prescaled by 1/N) ----
    fft8192_ip(sm, -1.f);

    // ---- fused wet/dry store: valid samples are second half j in [HOP, NFFT) ----
    const float wet = 1.f / (1.f + __expf(-wetp[0]));
    const float dry = 1.f - wet;
    const float* x0 = x + (size_t)(2 * pair) * T;
    const float* x1 = x + (size_t)(2 * pair + 1) * T;
    float* o0 = out + (size_t)(2 * pair) * T;
    float* o1 = out + (size_t)(2 * pair + 1) * T;
    for (int u = tid; u < HOP; u += NTH) {
        int n = t * HOP + u;
        if (n < T) {
            float2 y = sm[SWZ(HOP + u)];
            o0[n] = dry * x0[n] + wet * y.x;
            o1[n] = dry * x1[n] + wet * y.y;
        }
    }
}

// ---------------- launch ----------------
extern "C" void kernel_launch(void* const* d_in, const int* in_sizes, int n_in,
                              void* d_out, int out_size) {
    const float* x    = (const float*)d_in[0];
    const float* ir   = (const float*)d_in[1];
    const float* wetp = (const float*)d_in[2];
    float* out        = (float*)d_out;

    cudaFuncSetAttribute(hfft_kernel, cudaFuncAttributeMaxDynamicSharedMemorySize, SMEMB);
    cudaFuncSetAttribute(fwd_kernel, cudaFuncAttributeMaxDynamicSharedMemorySize, SMEMB);
    cudaFuncSetAttribute(out_kernel, cudaFuncAttributeMaxDynamicSharedMemorySize, SMEMB);

    twiddle_kernel<<<NFFT / 256, 256>>>();
    hfft_kernel<<<NP, NTH, SMEMB>>>(ir);
    fwd_kernel<<<NPAIR * NBLK, NTH, SMEMB>>>(x);
    out_kernel<<<NPAIR * NBLK, NTH, SMEMB>>>(x, wetp, out);
}

// round 11
// speedup vs baseline: 15.6513x; 1.1024x over previous
#include <cuda_runtime.h>
#include <cuda_fp16.h>
#include <cstdint>
#include <math.h>

#define DI __device__ __forceinline__

// ---------------- problem constants ----------------
constexpr int T     = 441000;
constexpr int L     = 44100;
constexpr int BATCH = 32;
constexpr int NFFT  = 8192;
constexpr int HOP   = 4096;
constexpr int NBLK  = 108;              // ceil(T / HOP)
constexpr int NP    = 11;               // ceil(L / HOP) IR partitions
constexpr int NPAIR = BATCH / 2;        // 16 complex-packed row pairs
constexpr int NTH   = 512;              // threads per FFT CTA (16 warps)

constexpr int SMEMB = NFFT * 8;         // 65536 B: single float2 buffer (in-place FFT)

// ---------------- global scratch ----------------
__device__ __align__(128) __half2 g_spec[(size_t)NPAIR * NBLK * NFFT];  // 54 MB (half2 spectra)
__device__ __align__(128) float2  g_H[(size_t)NP * NFFT];               // 704 KB fp32 (prescaled 1/N)
__device__ float2 g_tw[NFFT];                                           // e^{-2pi i t / NFFT}

// swizzle on float2 index: kills write bank conflicts, preserves read patterns
DI int SWZ(int a) { return a ^ ((a >> 4) & 15); }

// ---------------- register DFTs (sign sg=+1 fwd e^{-}, sg=-1 inv e^{+}) ----
DI void dft8(float* xr, float* xi, float sg) {
    const float c = 0.70710678118654752f;
    float t0r = xr[0] + xr[4], t0i = xi[0] + xi[4];
    float t1r = xr[0] - xr[4], t1i = xi[0] - xi[4];
    float t2r = xr[2] + xr[6], t2i = xi[2] + xi[6];
    float t3r = xr[2] - xr[6], t3i = xi[2] - xi[6];
    float w3r = sg * t3i, w3i = -sg * t3r;              // W4 * t3
    float E0r = t0r + t2r, E0i = t0i + t2i;
    float E1r = t1r + w3r, E1i = t1i + w3i;
    float E2r = t0r - t2r, E2i = t0i - t2i;
    float E3r = t1r - w3r, E3i = t1i - w3i;
    float u0r = xr[1] + xr[5], u0i = xi[1] + xi[5];
    float u1r = xr[1] - xr[5], u1i = xi[1] - xi[5];
    float u2r = xr[3] + xr[7], u2i = xi[3] + xi[7];
    float u3r = xr[3] - xr[7], u3i = xi[3] - xi[7];
    float v3r = sg * u3i, v3i = -sg * u3r;
    float O0r = u0r + u2r, O0i = u0i + u2i;
    float O1r = u1r + v3r, O1i = u1i + v3i;
    float O2r = u0r - u2r, O2i = u0i - u2i;
    float O3r = u1r - v3r, O3i = u1i - v3i;
    xr[0] = E0r + O0r; xi[0] = E0i + O0i;
    xr[4] = E0r - O0r; xi[4] = E0i - O0i;
    float p1r = c * (O1r + sg * O1i), p1i = c * (O1i - sg * O1r);   // W8^1 * O1
    xr[1] = E1r + p1r; xi[1] = E1i + p1i;
    xr[5] = E1r - p1r; xi[5] = E1i - p1i;
    float p2r = sg * O2i, p2i = -sg * O2r;                          // W8^2 * O2
    xr[2] = E2r + p2r; xi[2] = E2i + p2i;
    xr[6] = E2r - p2r; xi[6] = E2i - p2i;
    float p3r = c * (sg * O3i - O3r), p3i = -c * (O3i + sg * O3r);  // W8^3 * O3
    xr[3] = E3r + p3r; xi[3] = E3i + p3i;
    xr[7] = E3r - p3r; xi[7] = E3i - p3i;
}

DI void dft16(float* xr, float* xi, float sg) {
    const float C16[8] = {1.f, 0.92387953251128674f, 0.70710678118654752f, 0.38268343236508977f,
                          0.f, -0.38268343236508977f, -0.70710678118654752f, -0.92387953251128674f};
    const float S16[8] = {0.f, 0.38268343236508977f, 0.70710678118654752f, 0.92387953251128674f,
                          1.f, 0.92387953251128674f, 0.70710678118654752f, 0.38268343236508977f};
    float er[8], ei[8], orr[8], oii[8];
    #pragma unroll
    for (int j = 0; j < 8; j++) {
        er[j] = xr[2 * j];     ei[j] = xi[2 * j];
        orr[j] = xr[2 * j + 1]; oii[j] = xi[2 * j + 1];
    }
    dft8(er, ei, sg);
    dft8(orr, oii, sg);
    #pragma unroll
    for (int k = 0; k < 8; k++) {
        float wr = C16[k], wi = -S16[k] * sg;
        float pr = wr * orr[k] - wi * oii[k];
        float pi = wr * oii[k] + wi * orr[k];
        xr[k]     = er[k] + pr; xi[k]     = ei[k] + pi;
        xr[k + 8] = er[k] - pr; xi[k + 8] = ei[k] - pi;
    }
}

// ---------------- in-place Stockham stages (single float2 buffer) --------
template <int SS, int STEP>
DI void stage8_ip(float2* s, float sg) {
    float ar[2][8], ai[2][8];
    const int g0 = threadIdx.x;
    #pragma unroll
    for (int h = 0; h < 2; h++) {
        const int g = g0 + 512 * h;
        #pragma unroll
        for (int j = 0; j < 8; j++) {
            float2 v = s[SWZ(g + 1024 * j)];
            ar[h][j] = v.x; ai[h][j] = v.y;
        }
    }
    __syncthreads();
    #pragma unroll
    for (int h = 0; h < 2; h++) {
        const int g = g0 + 512 * h;
        const int p = g / SS;
        const int q = g - p * SS;
        dft8(ar[h], ai[h], sg);
        const int ob = q + SS * 8 * p;
        // k = 0: twiddle is exactly (1, 0) -> direct store
        s[SWZ(ob)] = make_float2(ar[h][0], ai[h][0]);
        #pragma unroll
        for (int k = 1; k < 8; k++) {
            int tix = (STEP * p * k) & (NFFT - 1);
            float2 w = g_tw[tix];
            float wi = w.y * sg;
            s[SWZ(ob + SS * k)] = make_float2(ar[h][k] * w.x - ai[h][k] * wi,
                                              ar[h][k] * wi + ai[h][k] * w.x);
        }
    }
    __syncthreads();
}

DI void stage16_ip(float2* s, float sg) {
    float ar[16], ai[16];
    const int g = threadIdx.x;
    #pragma unroll
    for (int j = 0; j < 16; j++) {
        float2 v = s[SWZ(g + 512 * j)];
        ar[j] = v.x; ai[j] = v.y;
    }
    __syncthreads();
    dft16(ar, ai, sg);
    #pragma unroll
    for (int k = 0; k < 16; k++)
        s[SWZ(g + 512 * k)] = make_float2(ar[k], ai[k]);
    __syncthreads();
}

// full 8192-pt complex FFT in-place over swizzled smem; natural order result.
DI void fft8192_ip(float2* s, float sg) {
    stage8_ip<1, 1>(s, sg);
    stage8_ip<8, 8>(s, sg);
    stage8_ip<64, 64>(s, sg);
    stage16_ip(s, sg);
}

// ---------------- kernels ----------------
__global__ void __launch_bounds__(256) twiddle_kernel() {
    int t = blockIdx.x * 256 + threadIdx.x;
    double s, c;
    sincos(2.0 * 3.14159265358979323846 * (double)t / (double)NFFT, &s, &c);
    g_tw[t] = make_float2((float)c, (float)(-s));
}

// fwd_kernel: blocks [0, NPAIR*NBLK) do x spectra; blocks [NPAIR*NBLK, +NP) do IR partitions
__global__ void __launch_bounds__(NTH, 2) fwd_kernel(const float* __restrict__ x,
                                                     const float* __restrict__ ir) {
    extern __shared__ float2 sm[];
    const int b = blockIdx.x;
    const int tid = threadIdx.x;

    if (b < NPAIR * NBLK) {
        const int pair = b / NBLK;
        const int t = b - pair * NBLK;
        const float* x0 = x + (size_t)(2 * pair) * T;
        const float* x1 = x + (size_t)(2 * pair + 1) * T;
        const int off = (t - 1) * HOP;      // multiple of 4096 (possibly negative)
        #pragma unroll
        for (int i = 0; i < 4; i++) {
            int j = 4 * (tid + NTH * i);
            int n = off + j;
            float4 v0 = make_float4(0.f, 0.f, 0.f, 0.f), v1 = v0;
            if (n >= 0 && n < T) {          // vector-aligned: n%4==0, T%4==0
                v0 = *(const float4*)(x0 + n);
                v1 = *(const float4*)(x1 + n);
            }
            sm[SWZ(j + 0)] = make_float2(v0.x, v1.x);
            sm[SWZ(j + 1)] = make_float2(v0.y, v1.y);
            sm[SWZ(j + 2)] = make_float2(v0.z, v1.z);
            sm[SWZ(j + 3)] = make_float2(v0.w, v1.w);
        }
        __syncthreads();
        fft8192_ip(sm, 1.f);
        uint4* dst = (uint4*)(g_spec + (size_t)b * NFFT);
        #pragma unroll
        for (int i = 0; i < 4; i++) {
            int k4 = tid + NTH * i;
            int kb = 4 * k4;
            float2 v0 = sm[SWZ(kb + 0)], v1 = sm[SWZ(kb + 1)];
            float2 v2 = sm[SWZ(kb + 2)], v3 = sm[SWZ(kb + 3)];
            uint4 o;
            *(__half2*)&o.x = __floats2half2_rn(v0.x, v0.y);
            *(__half2*)&o.y = __floats2half2_rn(v1.x, v1.y);
            *(__half2*)&o.z = __floats2half2_rn(v2.x, v2.y);
            *(__half2*)&o.w = __floats2half2_rn(v3.x, v3.y);
            dst[k4] = o;
        }
    } else {
        const int p = b - NPAIR * NBLK;
        for (int j = tid; j < NFFT; j += NTH) {
            int idx = p * HOP + j;
            float v = (j < HOP && idx < L) ? ir[idx] : 0.f;
            sm[SWZ(j)] = make_float2(v, 0.f);
        }
        __syncthreads();
        fft8192_ip(sm, 1.f);
        const float inv = 1.f / (float)NFFT;
        float2* dst = g_H + (size_t)p * NFFT;
        for (int k = tid; k < NFFT; k += NTH) {
            float2 v = sm[SWZ(k)];
            dst[k] = make_float2(v.x * inv, v.y * inv);
        }
    }
}

// complex MAC: 4 half2 X complexes (uint4) times 4 fp32 H complexes (2 x float4)
DI void cmac4(float4& a01, float4& a23, const uint4& xv,
              const float4& h01, const float4& h23) {
    const __half2* xh = (const __half2*)&xv;
    float2 x0 = __half22float2(xh[0]);
    float2 x1 = __half22float2(xh[1]);
    float2 x2 = __half22float2(xh[2]);
    float2 x3 = __half22float2(xh[3]);
    a01.x += x0.x * h01.x - x0.y * h01.y;
    a01.y += x0.x * h01.y + x0.y * h01.x;
    a01.z += x1.x * h01.z - x1.y * h01.w;
    a01.w += x1.x * h01.w + x1.y * h01.z;
    a23.x += x2.x * h23.x - x2.y * h23.y;
    a23.y += x2.x * h23.y + x2.y * h23.x;
    a23.z += x3.x * h23.z - x3.y * h23.w;
    a23.w += x3.x * h23.w + x3.y * h23.z;
}

__global__ void __launch_bounds__(NTH, 2) out_kernel(const float* __restrict__ x,
                                                     const float* __restrict__ wetp,
                                                     float* __restrict__ out) {
    extern __shared__ float2 sm[];
    const int b = blockIdx.x;
    const int pair = b / NBLK;
    const int t = b - pair * NBLK;
    const int tid = threadIdx.x;

    // ---- accumulate acc[k] = sum_p X[t-p][k] * H[p][k] ----
    float4 acc[8];
    #pragma unroll
    for (int i = 0; i < 8; i++) acc[i] = make_float4(0.f, 0.f, 0.f, 0.f);

    const uint4* Xbase = (const uint4*)(g_spec + (size_t)(pair * NBLK + t) * NFFT);

    if (t >= NP - 1) {
        #pragma unroll
        for (int p = 0; p < NP; p++) {
            const uint4* X4 = Xbase - (size_t)p * (NFFT / 4);
            const float4* H4 = (const float4*)(g_H + (size_t)p * NFFT);
            #pragma unroll
            for (int i = 0; i < 4; i++) {
                int f = tid + NTH * i;          // quad index: 4 complexes each
                uint4 xv = X4[f];
                float4 h01 = H4[2 * f];
                float4 h23 = H4[2 * f + 1];
                cmac4(acc[2 * i], acc[2 * i + 1], xv, h01, h23);
            }
        }
    } else {
        for (int p = 0; p <= t; p++) {
            const uint4* X4 = Xbase - (size_t)p * (NFFT / 4);
            const float4* H4 = (const float4*)(g_H + (size_t)p * NFFT);
            #pragma unroll
            for (int i = 0; i < 4; i++) {
                int f = tid + NTH * i;
                uint4 xv = X4[f];
                float4 h01 = H4[2 * f];
                float4 h23 = H4[2 * f + 1];
                cmac4(acc[2 * i], acc[2 * i + 1], xv, h01, h23);
            }
        }
    }
    #pragma unroll
    for (int i = 0; i < 4; i++) {
        int base = 4 * (tid + NTH * i);
        sm[SWZ(base + 0)] = make_float2(acc[2 * i].x, acc[2 * i].y);
        sm[SWZ(base + 1)] = make_float2(acc[2 * i].z, acc[2 * i].w);
        sm[SWZ(base + 2)] = make_float2(acc[2 * i + 1].x, acc[2 * i + 1].y);
        sm[SWZ(base + 3)] = make_float2(acc[2 * i + 1].z, acc[2 * i + 1].w);
    }
    __syncthreads();

    // ---- unnormalized inverse FFT (H prescaled by 1/N) ----
    fft8192_ip(sm, -1.f);

    // ---- fused wet/dry store: valid samples are second half j in [HOP, NFFT) ----
    const float wet = 1.f / (1.f + __expf(-wetp[0]));
    const float dry = 1.f - wet;
    const float* x0 = x + (size_t)(2 * pair) * T;
    const float* x1 = x + (size_t)(2 * pair + 1) * T;
    float* o0 = out + (size_t)(2 * pair) * T;
    float* o1 = out + (size_t)(2 * pair + 1) * T;
    #pragma unroll
    for (int i = 0; i < 2; i++) {
        int u = 4 * (tid + NTH * i);
        int n = t * HOP + u;
        if (n < T) {                         // n%4==0, T%4==0 -> whole vector valid
            float2 y0 = sm[SWZ(HOP + u + 0)];
            float2 y1 = sm[SWZ(HOP + u + 1)];
            float2 y2 = sm[SWZ(HOP + u + 2)];
            float2 y3 = sm[SWZ(HOP + u + 3)];
            float4 v0 = *(const float4*)(x0 + n);
            float4 v1 = *(const float4*)(x1 + n);
            float4 r0 = make_float4(dry * v0.x + wet * y0.x, dry * v0.y + wet * y1.x,
                                    dry * v0.z + wet * y2.x, dry * v0.w + wet * y3.x);
            float4 r1 = make_float4(dry * v1.x + wet * y0.y, dry * v1.y + wet * y1.y,
                                    dry * v1.z + wet * y2.y, dry * v1.w + wet * y3.y);
            *(float4*)(o0 + n) = r0;
            *(float4*)(o1 + n) = r1;
        }
    }
}

// ---------------- launch ----------------
extern "C" void kernel_launch(void* const* d_in, const int* in_sizes, int n_in,
                              void* d_out, int out_size) {
    const float* x    = (const float*)d_in[0];
    const float* ir   = (const float*)d_in[1];
    const float* wetp = (const float*)d_in[2];
    float* out        = (float*)d_out;

    cudaFuncSetAttribute(fwd_kernel, cudaFuncAttributeMaxDynamicSharedMemorySize, SMEMB);
    cudaFuncSetAttribute(out_kernel, cudaFuncAttributeMaxDynamicSharedMemorySize, SMEMB);

    twiddle_kernel<<<NFFT / 256, 256>>>();
    fwd_kernel<<<NPAIR * NBLK + NP, NTH, SMEMB>>>(x, ir);
    out_kernel<<<NPAIR * NBLK, NTH, SMEMB>>>(x, wetp, out);
}